// round 12
// baseline (speedup 1.0000x reference)
#include <cuda_runtime.h>
#include <cuda_bf16.h>
#include <math.h>
#include <stdint.h>

// ---------------- problem constants ----------------
#define kB    16
#define kLIN  400
#define kT    100
#define kD    512
#define kH    8
#define kDep  64
#define kDFF  2048
#define kV    32000
#define kOOV  100
#define kVE   (kV + kOOV)   // 32100

#define ME (kB * kLIN)      // 6400
#define MD (kB * kT)        // 1600

// packed-weight sizes (uint2 units = 2 elements each)
#define SZ_DD   (kD * kD / 2)
#define SZ_DFF  (kD * kDFF / 2)
#define SZ_FW   (kD * kV / 2)
#define WP_TOTAL (16 * SZ_DD + 6 * SZ_DFF + SZ_FW)

// ---------------- scratch (device globals; no runtime alloc) ----------------
__device__ float g_pe [kLIN * kD];
__device__ float g_xe [ME * kD];
__device__ float g_q  [ME * kD];
__device__ float g_k  [ME * kD];
__device__ float g_v  [ME * kD];
__device__ float g_t  [ME * kD];
__device__ float g_cs [kB * kH * kT * kLIN];   // cross probs (block2)
__device__ float g_xd [MD * kD];
__device__ float g_emb[MD * kD];
__device__ float g_o1 [MD * kD];
__device__ float g_o2 [MD * kD];
__device__ float g_do [MD * kD];
__device__ float g_pg [MD];
__device__ float g_am [MD * kLIN];
__device__ uint2 g_wp [WP_TOTAL];
__device__ uint2 g_pa0[ME * kD / 2];       // packed residual stream (x)
__device__ uint2 g_paT[ME * kD / 2];       // packed attention output
__device__ uint2 g_pa1[ME * kDFF / 2];     // packed ffn hidden
__device__ uint2 g_pa2[MD * kD / 2];       // packed decoder stream

// ---------------- helpers ----------------
__device__ __forceinline__ float warp_sum(float v) {
    #pragma unroll
    for (int o = 16; o > 0; o >>= 1) v += __shfl_xor_sync(0xffffffffu, v, o);
    return v;
}
__device__ __forceinline__ float warp_max(float v) {
    #pragma unroll
    for (int o = 16; o > 0; o >>= 1) v = fmaxf(v, __shfl_xor_sync(0xffffffffu, v, o));
    return v;
}
__device__ __forceinline__ uint2 bfsplit2(float f0, float f1) {
    uint32_t hi;
    asm("cvt.rn.bf16x2.f32 %0, %1, %2;" : "=r"(hi) : "f"(f1), "f"(f0));
    __nv_bfloat162 h = *reinterpret_cast<__nv_bfloat162*>(&hi);
    float r0 = f0 - __bfloat162float(h.x);
    float r1 = f1 - __bfloat162float(h.y);
    uint32_t lo;
    asm("cvt.rn.bf16x2.f32 %0, %1, %2;" : "=r"(lo) : "f"(r1), "f"(r0));
    return make_uint2(hi, lo);
}
__device__ __forceinline__ void mma_bf16(float (&d)[4], const uint32_t (&a)[4], const uint32_t (&b)[2]) {
    asm volatile(
        "mma.sync.aligned.m16n8k16.row.col.f32.bf16.bf16.f32 "
        "{%0,%1,%2,%3},{%4,%5,%6,%7},{%8,%9},{%0,%1,%2,%3};"
        : "+f"(d[0]), "+f"(d[1]), "+f"(d[2]), "+f"(d[3])
        : "r"(a[0]), "r"(a[1]), "r"(a[2]), "r"(a[3]), "r"(b[0]), "r"(b[1]));
}

// ---------------- one-shot weight pack (all matrices, one launch) ----------------
// segments in g_wp order: eaw(8 x DD) | ew1(2 x DFF) | ew2(2 x DFF) | daw L1 (8 x DD)
//                         | dw1 L1 (DFF) | dw2 L1 (DFF) | fw (FW)
__global__ void pack_all_kernel(const float* __restrict__ eaw, const float* __restrict__ ew1,
                                const float* __restrict__ ew2, const float* __restrict__ daw,
                                const float* __restrict__ dw1, const float* __restrict__ dw2,
                                const float* __restrict__ fw,  uint2* __restrict__ out) {
    long i = (long)blockIdx.x * 256 + threadIdx.x;
    if (i >= (long)WP_TOTAL) return;
    const long B0 = 8L * SZ_DD;
    const long B1 = B0 + 2L * SZ_DFF;
    const long B2 = B1 + 2L * SZ_DFF;
    const long B3 = B2 + 8L * SZ_DD;
    const long B4 = B3 + (long)SZ_DFF;
    const long B5 = B4 + (long)SZ_DFF;
    const float* src; int N; long p;
    if (i < B0)      { long m = i / SZ_DD;        p = i - m * SZ_DD;  src = eaw + m * (long)kD * kD;        N = kD;   }
    else if (i < B1) { long j = i - B0; long m = j / SZ_DFF; p = j - m * SZ_DFF; src = ew1 + m * (long)kD * kDFF; N = kDFF; }
    else if (i < B2) { long j = i - B1; long m = j / SZ_DFF; p = j - m * SZ_DFF; src = ew2 + m * (long)kDFF * kD; N = kD;   }
    else if (i < B3) { long j = i - B2; long m = j / SZ_DD;  p = j - m * SZ_DD;  src = daw + (8 + m) * (long)kD * kD; N = kD; }
    else if (i < B4) { p = i - B3; src = dw1 + (long)kD * kDFF;  N = kDFF; }
    else if (i < B5) { p = i - B4; src = dw2 + (long)kDFF * kD;  N = kD;   }
    else             { p = i - B5; src = fw;                     N = kV;   }
    long kp = p / N, n = p - kp * N;
    out[i] = bfsplit2(src[(2 * kp) * (long)N + n], src[(2 * kp + 1) * (long)N + n]);
}

// ---------------- positional encoding ----------------
__global__ void pe_kernel(float* __restrict__ pe) {
    int i = blockIdx.x * 256 + threadIdx.x;
    if (i >= kLIN * kD) return;
    int pos = i / kD, d = i % kD;
    double rate = exp(-(double)(2 * (d / 2)) / (double)kD * log(10000.0));
    double ang  = (double)pos * rate;
    pe[i] = (float)((d & 1) ? cos(ang) : sin(ang));
}

// ---------------- embeddings (emit float + packed) ----------------
__global__ void embed_enc_kernel(const int* __restrict__ idx, const float* __restrict__ emb,
                                 const float* __restrict__ pe, float* __restrict__ x,
                                 uint2* __restrict__ xpk) {
    int i = blockIdx.x * 256 + threadIdx.x;
    if (i >= ME * kD / 2) return;
    int dp = i & 255;
    int bs = i >> 8;
    int s  = bs % kLIN;
    int d  = dp << 1;
    float2 e = *(const float2*)&emb[(size_t)idx[bs] * kD + d];
    float2 p = *(const float2*)&pe[s * kD + d];
    float scale = sqrtf((float)kD);
    float x0 = e.x * scale + p.x, x1 = e.y * scale + p.y;
    *(float2*)&x[(size_t)bs * kD + d] = make_float2(x0, x1);
    xpk[i] = bfsplit2(x0, x1);
}
__global__ void embed_dec_kernel(const int* __restrict__ idx, const float* __restrict__ emb,
                                 const float* __restrict__ pe, float* __restrict__ x,
                                 uint2* __restrict__ xpk, float* __restrict__ eraw) {
    int i = blockIdx.x * 256 + threadIdx.x;
    if (i >= MD * kD / 2) return;
    int dp = i & 255;
    int bs = i >> 8;
    int s  = bs % kT;
    int d  = dp << 1;
    float2 e = *(const float2*)&emb[(size_t)idx[bs] * kD + d];
    float2 p = *(const float2*)&pe[s * kD + d];
    *(float2*)&eraw[(size_t)bs * kD + d] = e;
    float scale = sqrtf((float)kD);
    float x0 = e.x * scale + p.x, x1 = e.y * scale + p.y;
    *(float2*)&x[(size_t)bs * kD + d] = make_float2(x0, x1);
    xpk[i] = bfsplit2(x0, x1);
}

// ---------------- bf16 3-term tensor-core GEMM (tile 64x256) ----------------
// C[M,N] = A[M,K] @ W[K,N] + bias (+relu, +row-scale | packout). Pre-packed hi/lo.
// BK=32 (16 kpairs), 256 threads = 8 warps (2M x 4N), warp tile 32x64.
// Same sync-load-sync-compute structure as the proven R8 kernel; only tiling widened.
// Requires M%64==0, N%256==0, K%32==0.
__global__ void __launch_bounds__(256, 2)
gemm_bf16_kernel(const uint2* __restrict__ Ap, const uint2* __restrict__ Wp,
                 const float* __restrict__ bias, float* __restrict__ C,
                 int M, int N, int K, int ldc, int relu, const float* __restrict__ rs,
                 int packout) {
    __shared__ uint2 As[16][68];     // [kpair][m]
    __shared__ uint2 Bs[16][260];    // [kpair][n]  (260 % 32... 520 words %32 = 8 -> conflict-free)

    const int t = threadIdx.x, lane = t & 31, wid = t >> 5;
    const int wm = wid & 1, wn = wid >> 1;          // 2 x 4 warps
    const int g = lane >> 2, c = lane & 3;
    const int bm = blockIdx.y << 6, bn = blockIdx.x << 8;
    const int a_row = t & 63, a_kq = (t >> 6) << 2;
    const int b_kp = t >> 4, b_n = (t & 15) << 1;   // 8 uint4 chunks at +0,32,..,224
    const int Kp = K >> 1;

    const uint2* aptr = Ap + (size_t)(bm + a_row) * Kp + a_kq;
    float acc[2][8][4] = {};

    for (int kp0 = 0; kp0 < Kp; kp0 += 16) {
        uint4 av0 = *(const uint4*)(aptr + kp0);
        uint4 av1 = *(const uint4*)(aptr + kp0 + 2);
        const uint2* wrow = Wp + (size_t)(kp0 + b_kp) * N + bn + b_n;
        uint4 bv[8];
        #pragma unroll
        for (int p = 0; p < 8; ++p) bv[p] = *(const uint4*)(wrow + 32 * p);
        __syncthreads();
        As[a_kq + 0][a_row] = make_uint2(av0.x, av0.y);
        As[a_kq + 1][a_row] = make_uint2(av0.z, av0.w);
        As[a_kq + 2][a_row] = make_uint2(av1.x, av1.y);
        As[a_kq + 3][a_row] = make_uint2(av1.z, av1.w);
        #pragma unroll
        for (int p = 0; p < 8; ++p) *(uint4*)&Bs[b_kp][b_n + 32 * p] = bv[p];
        __syncthreads();
        #pragma unroll
        for (int s = 0; s < 2; ++s) {              // two k16 steps
            const int sb = s << 3;
            uint2 af[2][4];
            #pragma unroll
            for (int mi = 0; mi < 2; ++mi) {
                int m = (wm << 5) + (mi << 4) + g;
                af[mi][0] = As[sb + c][m];
                af[mi][1] = As[sb + c][m + 8];
                af[mi][2] = As[sb + c + 4][m];
                af[mi][3] = As[sb + c + 4][m + 8];
            }
            #pragma unroll
            for (int nh = 0; nh < 2; ++nh) {       // two n-halves keep regs low
                uint2 bf[4][2];
                #pragma unroll
                for (int ni = 0; ni < 4; ++ni) {
                    int n = (wn << 6) + (nh << 5) + (ni << 3) + g;
                    bf[ni][0] = Bs[sb + c][n];
                    bf[ni][1] = Bs[sb + c + 4][n];
                }
                #pragma unroll
                for (int mi = 0; mi < 2; ++mi) {
                    uint32_t ah[4] = {af[mi][0].x, af[mi][1].x, af[mi][2].x, af[mi][3].x};
                    uint32_t al[4] = {af[mi][0].y, af[mi][1].y, af[mi][2].y, af[mi][3].y};
                    #pragma unroll
                    for (int ni = 0; ni < 4; ++ni) {
                        uint32_t bh[2] = {bf[ni][0].x, bf[ni][1].x};
                        uint32_t bl[2] = {bf[ni][0].y, bf[ni][1].y};
                        mma_bf16(acc[mi][(nh << 2) + ni], al, bh);
                        mma_bf16(acc[mi][(nh << 2) + ni], ah, bl);
                        mma_bf16(acc[mi][(nh << 2) + ni], ah, bh);
                    }
                }
            }
        }
    }

    // ---- epilogue ----
    #pragma unroll
    for (int mi = 0; mi < 2; ++mi) {
        int r0 = bm + (wm << 5) + (mi << 4) + g;
        float s0 = rs ? rs[r0] : 1.0f;
        float s1 = rs ? rs[r0 + 8] : 1.0f;
        #pragma unroll
        for (int nj = 0; nj < 8; ++nj) {
            int c0 = bn + (wn << 6) + (nj << 3) + (c << 1);
            float bb0 = bias[c0], bb1 = bias[c0 + 1];
            float v0 = acc[mi][nj][0] + bb0, v1 = acc[mi][nj][1] + bb1;
            float v2 = acc[mi][nj][2] + bb0, v3 = acc[mi][nj][3] + bb1;
            if (relu) {
                v0 = fmaxf(v0, 0.0f); v1 = fmaxf(v1, 0.0f);
                v2 = fmaxf(v2, 0.0f); v3 = fmaxf(v3, 0.0f);
            }
            if (packout) {
                uint2* Cp = (uint2*)C;
                int ldp = ldc >> 1;
                Cp[(size_t)r0 * ldp + (c0 >> 1)]       = bfsplit2(v0 * s0, v1 * s0);
                Cp[(size_t)(r0 + 8) * ldp + (c0 >> 1)] = bfsplit2(v2 * s1, v3 * s1);
            } else {
                *(float2*)&C[(size_t)r0 * ldc + c0]       = make_float2(v0 * s0, v1 * s0);
                *(float2*)&C[(size_t)(r0 + 8) * ldc + c0] = make_float2(v2 * s1, v3 * s1);
            }
        }
    }
}

// ---------------- fused attention: scores -> softmax -> P@V, packed output ------
#define ATTN_SMEM_BYTES ((32*408 + 32*68 + 32*68) * 4)
__global__ void __launch_bounds__(256)
fused_attn_kernel(const float* __restrict__ Q, const float* __restrict__ Kt,
                  const float* __restrict__ V, uint2* __restrict__ Opk,
                  int Sq, int Sk, const float* __restrict__ mask, int mode,
                  float* __restrict__ Pout) {
    extern __shared__ float sm_f[];
    float (*Ss)[408] = (float(*)[408])sm_f;
    float (*Qs)[68]  = (float(*)[68])(sm_f + 32 * 408);
    float (*Ks)[68]  = (float(*)[68])(sm_f + 32 * 408 + 32 * 68);

    const int tid = threadIdx.x;
    const int bh = blockIdx.y, b = bh >> 3, h = bh & 7;
    const int q0 = blockIdx.x * 32;

    for (int i = tid; i < 32 * 16; i += 256) {
        int r = i >> 4, c4 = (i & 15) << 2;
        float4 qv = make_float4(0, 0, 0, 0);
        if (q0 + r < Sq) qv = *(const float4*)&Q[((size_t)(b * Sq + q0 + r)) * kD + h * kDep + c4];
        *(float4*)&Qs[r][c4] = qv;
    }

    const int tx = tid & 15, ty = tid >> 4;
    for (int k0 = 0; k0 < Sk; k0 += 32) {
        for (int i = tid; i < 32 * 16; i += 256) {
            int r = i >> 4, c4 = (i & 15) << 2;
            float4 kv = make_float4(0, 0, 0, 0);
            if (k0 + r < Sk) kv = *(const float4*)&Kt[((size_t)(b * Sk + k0 + r)) * kD + h * kDep + c4];
            *(float4*)&Ks[r][c4] = kv;
        }
        __syncthreads();
        float acc[2][2] = {};
        #pragma unroll
        for (int d4 = 0; d4 < kDep; d4 += 4) {
            float4 a0 = *(const float4*)&Qs[ty * 2 + 0][d4];
            float4 a1 = *(const float4*)&Qs[ty * 2 + 1][d4];
            float4 b0 = *(const float4*)&Ks[tx * 2 + 0][d4];
            float4 b1 = *(const float4*)&Ks[tx * 2 + 1][d4];
            acc[0][0] += a0.x*b0.x + a0.y*b0.y + a0.z*b0.z + a0.w*b0.w;
            acc[0][1] += a0.x*b1.x + a0.y*b1.y + a0.z*b1.z + a0.w*b1.w;
            acc[1][0] += a1.x*b0.x + a1.y*b0.y + a1.z*b0.z + a1.w*b0.w;
            acc[1][1] += a1.x*b1.x + a1.y*b1.y + a1.z*b1.z + a1.w*b1.w;
        }
        #pragma unroll
        for (int i = 0; i < 2; ++i) {
            int qg = q0 + ty * 2 + i;
            #pragma unroll
            for (int j = 0; j < 2; ++j) {
                int kg = k0 + tx * 2 + j;
                if (qg < Sq && kg < Sk) {
                    float vv = acc[i][j] * 0.125f;
                    float mk = (mode == 0) ? mask[(size_t)b * Sk + kg]
                                           : mask[((size_t)b * Sq + qg) * Sk + kg];
                    Ss[ty * 2 + i][kg] = vv + mk * (-1e9f);
                }
            }
        }
        __syncthreads();
    }

    {
        const int wid = tid >> 5, lane = tid & 31;
        #pragma unroll
        for (int rr = 0; rr < 4; ++rr) {
            int r = (wid << 2) + rr;
            if (q0 + r < Sq) {
                float m = -1e30f;
                for (int i = lane; i < Sk; i += 32) m = fmaxf(m, Ss[r][i]);
                m = warp_max(m);
                float s = 0.0f;
                for (int i = lane; i < Sk; i += 32) { float e = __expf(Ss[r][i] - m); Ss[r][i] = e; s += e; }
                s = warp_sum(s);
                float inv = 1.0f / s;
                for (int i = lane; i < Sk; i += 32) Ss[r][i] *= inv;
            }
        }
    }
    __syncthreads();

    if (Pout) {
        for (int idx = tid; idx < 32 * Sk; idx += 256) {
            int r = idx / Sk, col = idx - r * Sk;
            if (q0 + r < Sq)
                Pout[((size_t)bh * Sq + q0 + r) * Sk + col] = Ss[r][col];
        }
    }

    const int dcol = tid & 63, qb = tid >> 6;
    float acc[8] = {};
    for (int k0 = 0; k0 < Sk; k0 += 32) {
        for (int i = tid; i < 32 * 16; i += 256) {
            int r = i >> 4, c4 = (i & 15) << 2;
            float4 v4 = make_float4(0, 0, 0, 0);
            if (k0 + r < Sk) v4 = *(const float4*)&V[((size_t)(b * Sk + k0 + r)) * kD + h * kDep + c4];
            *(float4*)&Ks[r][c4] = v4;
        }
        __syncthreads();
        int klim = Sk - k0; if (klim > 32) klim = 32;
        for (int kk = 0; kk < klim; ++kk) {
            float vv = Ks[kk][dcol];
            #pragma unroll
            for (int j = 0; j < 8; ++j)
                acc[j] = fmaf(Ss[qb + (j << 2)][k0 + kk], vv, acc[j]);
        }
        __syncthreads();
    }
    #pragma unroll
    for (int j = 0; j < 8; ++j) {
        float other = __shfl_xor_sync(0xffffffffu, acc[j], 1);
        int qg = q0 + qb + (j << 2);
        if (((dcol & 1) == 0) && qg < Sq) {
            Opk[((size_t)(b * Sq + qg)) * (kD / 2) + ((h * kDep + dcol) >> 1)] =
                bfsplit2(acc[j], other);
        }
    }
}

// ---------------- context einsum: O = P @ V (float, pointer head only) ----------
__global__ void __launch_bounds__(256)
attn_out_kernel(const float* __restrict__ P, const float* __restrict__ V,
                float* __restrict__ O, int Sq, int Sk) {
    __shared__ float Ps[32][33];
    __shared__ float Vs[32][64];
    int tid = threadIdx.x;
    int bh = blockIdx.y, b = bh >> 3, h = bh & 7;
    int q0 = blockIdx.x * 32;
    const float* p = P + (size_t)bh * Sq * Sk;
    int dcol = tid & 63, qb = tid >> 6;
    float acc[8] = {};
    for (int k0 = 0; k0 < Sk; k0 += 32) {
        {
            int r = tid >> 3, cc = (tid & 7) << 2;
            int qg = q0 + r, kg = k0 + cc;
            float4 v4 = make_float4(0, 0, 0, 0);
            if (qg < Sq && kg < Sk)
                v4 = *(const float4*)&p[(size_t)qg * Sk + kg];
            Ps[r][cc] = v4.x; Ps[r][cc + 1] = v4.y; Ps[r][cc + 2] = v4.z; Ps[r][cc + 3] = v4.w;
        }
        for (int i = tid; i < 32 * 16; i += 256) {
            int r = i >> 4, c4 = (i & 15) << 2;
            int kg = k0 + r;
            float4 v4 = make_float4(0, 0, 0, 0);
            if (kg < Sk) v4 = *(const float4*)&V[((size_t)(b * Sk + kg)) * kD + h * kDep + c4];
            *(float4*)&Vs[r][c4] = v4;
        }
        __syncthreads();
        #pragma unroll
        for (int kk = 0; kk < 32; ++kk) {
            float vv = Vs[kk][dcol];
            #pragma unroll
            for (int j = 0; j < 8; ++j)
                acc[j] = fmaf(Ps[qb + (j << 2)][kk], vv, acc[j]);
        }
        __syncthreads();
    }
    #pragma unroll
    for (int j = 0; j < 8; ++j) {
        int qg = q0 + qb + (j << 2);
        if (qg < Sq) O[((size_t)(b * Sq + qg)) * kD + h * kDep + dcol] = acc[j];
    }
}

// ---------------- y = LN(x + a) * g + b, emits float + packed ----------------
__global__ void add_ln_kernel(const float* __restrict__ x, const float* __restrict__ a,
                              float* __restrict__ y, uint2* __restrict__ ypk,
                              const float* __restrict__ g, const float* __restrict__ bb) {
    int row = blockIdx.x, tid = threadIdx.x;
    size_t base = (size_t)row * kD;
    int d0 = tid << 2;
    float4 xv = *(const float4*)&x[base + d0];
    float4 av = *(const float4*)&a[base + d0];
    float v0 = xv.x + av.x, v1 = xv.y + av.y, v2 = xv.z + av.z, v3 = xv.w + av.w;
    float s = v0 + v1 + v2 + v3;
    float s2 = v0*v0 + v1*v1 + v2*v2 + v3*v3;
    __shared__ float shs[4], shs2[4];
    s = warp_sum(s); s2 = warp_sum(s2);
    if ((tid & 31) == 0) { shs[tid >> 5] = s; shs2[tid >> 5] = s2; }
    __syncthreads();
    float S = shs[0] + shs[1] + shs[2] + shs[3];
    float S2 = shs2[0] + shs2[1] + shs2[2] + shs2[3];
    float mu = S * (1.0f / kD);
    float var = S2 * (1.0f / kD) - mu * mu;
    float rstd = rsqrtf(var + 1e-6f);
    float4 gv = *(const float4*)&g[d0];
    float4 bv = *(const float4*)&bb[d0];
    float y0 = (v0 - mu) * rstd * gv.x + bv.x;
    float y1 = (v1 - mu) * rstd * gv.y + bv.y;
    float y2 = (v2 - mu) * rstd * gv.z + bv.z;
    float y3 = (v3 - mu) * rstd * gv.w + bv.w;
    *(float4*)&y[base + d0] = make_float4(y0, y1, y2, y3);
    uint2 p0 = bfsplit2(y0, y1), p1 = bfsplit2(y2, y3);
    *(uint4*)&ypk[(size_t)row * (kD / 2) + (tid << 1)] = make_uint4(p0.x, p0.y, p1.x, p1.y);
}

// ---------------- p_gen ----------------
__global__ void pgen_kernel(const float* __restrict__ ctx, const float* __restrict__ dec,
                            const float* __restrict__ emb, const float* __restrict__ w,
                            const float* __restrict__ bvec, float* __restrict__ pg) {
    int row = blockIdx.x, tid = threadIdx.x;
    float s = 0.0f;
    for (int d = tid; d < kD; d += 128) {
        size_t o = (size_t)row * kD + d;
        s += ctx[o] * w[d] + dec[o] * w[kD + d] + emb[o] * w[2 * kD + d];
    }
    __shared__ float sh[4];
    s = warp_sum(s);
    if ((tid & 31) == 0) sh[tid >> 5] = s;
    __syncthreads();
    if (tid == 0) {
        float t = sh[0] + sh[1] + sh[2] + sh[3] + bvec[0] + bvec[1] + bvec[2];
        pg[row] = 1.0f / (1.0f + expf(-t));
    }
}

// ---------------- attn_mean ----------------
__global__ void attn_mean_kernel(const float* __restrict__ P, float* __restrict__ am) {
    int i = blockIdx.x * 256 + threadIdx.x;
    if (i >= MD * kLIN) return;
    int l = i % kLIN;
    int bt = i / kLIN;
    int b = bt / kT, t = bt % kT;
    float s = 0.0f;
    #pragma unroll
    for (int h = 0; h < kH; ++h)
        s += P[(((size_t)(b * kH + h) * kT) + t) * kLIN + l];
    am[i] = s * (1.0f / kH);
}

// ---------------- zero extension columns ----------------
__global__ void zero_ext_kernel(float* __restrict__ out) {
    int i = blockIdx.x * 256 + threadIdx.x;
    if (i >= MD * kOOV) return;
    int row = i / kOOV, c = i % kOOV;
    out[(size_t)row * kVE + kV + c] = 0.0f;
}

// ---------------- copy scatter ----------------
__global__ void scatter_kernel(float* __restrict__ out, const float* __restrict__ am,
                               const float* __restrict__ pg, const int* __restrict__ ext) {
    int i = blockIdx.x * 256 + threadIdx.x;
    if (i >= MD * kLIN) return;
    int l = i % kLIN;
    int bt = i / kLIN;
    int b = bt / kT;
    float v = (1.0f - pg[bt]) * am[i];
    int vi = ext[b * kLIN + l];
    atomicAdd(&out[(size_t)bt * kVE + vi], v);
}

// ---------------- host orchestration ----------------
extern "C" void kernel_launch(void* const* d_in, const int* in_sizes, int n_in,
                              void* d_out, int out_size) {
    int off = (n_in > 6 && in_sizes[6] == 1) ? 1 : 0;
    const int*   inp      = (const int*)d_in[0];
    const int*   tar      = (const int*)d_in[1];
    const int*   ext      = (const int*)d_in[2];
    const float* enc_mask = (const float*)d_in[3];
    const float* la_mask  = (const float*)d_in[4];
    const float* dec_mask = (const float*)d_in[5];
    const float* emb_enc  = (const float*)d_in[6 + off];
    const float* emb_dec  = (const float*)d_in[7 + off];
    const float* eaw = (const float*)d_in[8 + off];
    const float* eab = (const float*)d_in[9 + off];
    const float* ew1 = (const float*)d_in[10 + off];
    const float* eb1 = (const float*)d_in[11 + off];
    const float* ew2 = (const float*)d_in[12 + off];
    const float* eb2 = (const float*)d_in[13 + off];
    const float* elg = (const float*)d_in[14 + off];
    const float* elb = (const float*)d_in[15 + off];
    const float* daw = (const float*)d_in[16 + off];
    const float* dab = (const float*)d_in[17 + off];
    const float* dw1 = (const float*)d_in[18 + off];
    const float* db1 = (const float*)d_in[19 + off];
    const float* dw2 = (const float*)d_in[20 + off];
    const float* db2 = (const float*)d_in[21 + off];
    const float* dlg = (const float*)d_in[22 + off];
    const float* dlb = (const float*)d_in[23 + off];
    const float* ptrw = (const float*)d_in[24 + off];
    const float* ptrb = (const float*)d_in[25 + off];
    const float* fw  = (const float*)d_in[26 + off];
    const float* fb  = (const float*)d_in[27 + off];
    float* out = (float*)d_out;

    float *pe_, *xe_, *q_, *k_, *v_, *t_, *cs_, *xd_, *emb_, *o1_, *o2_, *do_, *pg_, *am_;
    uint2 *wp_, *pa0_, *paT_, *pa1_, *pa2_;
    cudaGetSymbolAddress((void**)&pe_,  g_pe);
    cudaGetSymbolAddress((void**)&xe_,  g_xe);
    cudaGetSymbolAddress((void**)&q_,   g_q);
    cudaGetSymbolAddress((void**)&k_,   g_k);
    cudaGetSymbolAddress((void**)&v_,   g_v);
    cudaGetSymbolAddress((void**)&t_,   g_t);
    cudaGetSymbolAddress((void**)&cs_,  g_cs);
    cudaGetSymbolAddress((void**)&xd_,  g_xd);
    cudaGetSymbolAddress((void**)&emb_, g_emb);
    cudaGetSymbolAddress((void**)&o1_,  g_o1);
    cudaGetSymbolAddress((void**)&o2_,  g_o2);
    cudaGetSymbolAddress((void**)&do_,  g_do);
    cudaGetSymbolAddress((void**)&pg_,  g_pg);
    cudaGetSymbolAddress((void**)&am_,  g_am);
    cudaGetSymbolAddress((void**)&wp_,  g_wp);
    cudaGetSymbolAddress((void**)&pa0_, g_pa0);
    cudaGetSymbolAddress((void**)&paT_, g_paT);
    cudaGetSymbolAddress((void**)&pa1_, g_pa1);
    cudaGetSymbolAddress((void**)&pa2_, g_pa2);

    cudaFuncSetAttribute(fused_attn_kernel, cudaFuncAttributeMaxDynamicSharedMemorySize, ATTN_SMEM_BYTES);

    const size_t o_eaw = 0;
    const size_t o_ew1 = o_eaw + 8 * (size_t)SZ_DD;
    const size_t o_ew2 = o_ew1 + 2 * (size_t)SZ_DFF;
    const size_t o_daw = o_ew2 + 2 * (size_t)SZ_DFF;
    const size_t o_dw1 = o_daw + 8 * (size_t)SZ_DD;
    const size_t o_dw2 = o_dw1 + (size_t)SZ_DFF;
    const size_t o_fw  = o_dw2 + (size_t)SZ_DFF;

    auto gemm = [&](const uint2* Ap, const uint2* Wp, const float* bias, float* C,
                    int M, int N, int K, int ldc, int relu, const float* rs, int packout = 0) {
        dim3 grid(N / 256, M / 64);
        gemm_bf16_kernel<<<grid, 256>>>(Ap, Wp, bias, C, M, N, K, ldc, relu, rs, packout);
    };
    auto attn = [&](const float* Q, const float* Kt, const float* V, uint2* Opk,
                    int Sq, int Sk, const float* mask, int mode, float* Pout) {
        dim3 grid((Sq + 31) / 32, kB * kH);
        fused_attn_kernel<<<grid, 256, ATTN_SMEM_BYTES>>>(Q, Kt, V, Opk, Sq, Sk, mask, mode, Pout);
    };

    // -------- pack ALL weights in one launch --------
    pack_all_kernel<<<(WP_TOTAL + 255) / 256, 256>>>(eaw, ew1, ew2, daw, dw1, dw2, fw, wp_);

    pe_kernel<<<(kLIN * kD + 255) / 256, 256>>>(pe_);
    embed_enc_kernel<<<(ME * kD / 2 + 255) / 256, 256>>>(inp, emb_enc, pe_, xe_, pa0_);

    // ================= encoder =================
    for (int i = 0; i < 2; ++i) {
        const uint2* w = wp_ + o_eaw + (size_t)i * 4 * SZ_DD;
        const float* b = eab + (size_t)i * 4 * kD;
        gemm(pa0_, w + 0 * SZ_DD, b + 0 * kD, q_, ME, kD, kD, kD, 0, nullptr);
        gemm(pa0_, w + 1 * SZ_DD, b + 1 * kD, k_, ME, kD, kD, kD, 0, nullptr);
        gemm(pa0_, w + 2 * SZ_DD, b + 2 * kD, v_, ME, kD, kD, kD, 0, nullptr);
        attn(q_, k_, v_, paT_, kLIN, kLIN, enc_mask, 0, nullptr);
        gemm(paT_, w + 3 * SZ_DD, b + 3 * kD, q_, ME, kD, kD, kD, 0, nullptr);
        add_ln_kernel<<<ME, 128>>>(xe_, q_, xe_, pa0_, elg + (i * 2 + 0) * kD, elb + (i * 2 + 0) * kD);
        gemm(pa0_, wp_ + o_ew1 + (size_t)i * SZ_DFF, eb1 + (size_t)i * kDFF,
             (float*)pa1_, ME, kDFF, kD, kDFF, 1, nullptr, 1);
        gemm(pa1_, wp_ + o_ew2 + (size_t)i * SZ_DFF, eb2 + (size_t)i * kD, q_, ME, kD, kDFF, kD, 0, nullptr);
        add_ln_kernel<<<ME, 128>>>(xe_, q_, xe_, pa0_, elg + (i * 2 + 1) * kD, elb + (i * 2 + 1) * kD);
    }
    // pa0_ now holds the packed final encoder output (for cross K/V)

    // ================= decoder (only layer 1 live; xd never updated in ref) ========
    embed_dec_kernel<<<(MD * kD / 2 + 255) / 256, 256>>>(tar, emb_dec, pe_, xd_, pa2_, emb_);
    {
        const uint2* w0 = wp_ + o_daw;
        const uint2* w1 = wp_ + o_daw + 4 * (size_t)SZ_DD;
        const float* b0 = dab + (size_t)(1 * 2 + 0) * 4 * kD;
        const float* b1 = dab + (size_t)(1 * 2 + 1) * 4 * kD;
        gemm(pa2_, w0 + 0 * SZ_DD, b0 + 0 * kD, q_, MD, kD, kD, kD, 0, nullptr);
        gemm(pa2_, w0 + 1 * SZ_DD, b0 + 1 * kD, k_, MD, kD, kD, kD, 0, nullptr);
        gemm(pa2_, w0 + 2 * SZ_DD, b0 + 2 * kD, v_, MD, kD, kD, kD, 0, nullptr);
        attn(q_, k_, v_, pa2_, kT, kT, la_mask, 1, nullptr);
        gemm(pa2_, w0 + 3 * SZ_DD, b0 + 3 * kD, q_, MD, kD, kD, kD, 0, nullptr);
        add_ln_kernel<<<MD, 128>>>(xd_, q_, o1_, pa2_, dlg + (1 * 3 + 0) * kD, dlb + (1 * 3 + 0) * kD);
        // cross attention
        gemm(pa2_, w1 + 0 * SZ_DD, b1 + 0 * kD, q_, MD, kD, kD, kD, 0, nullptr);
        gemm(pa0_, w1 + 1 * SZ_DD, b1 + 1 * kD, k_, ME, kD, kD, kD, 0, nullptr);
        gemm(pa0_, w1 + 2 * SZ_DD, b1 + 2 * kD, v_, ME, kD, kD, kD, 0, nullptr);
        attn(q_, k_, v_, pa2_, kT, kLIN, dec_mask, 0, cs_);
        gemm(pa2_, w1 + 3 * SZ_DD, b1 + 3 * kD, q_, MD, kD, kD, kD, 0, nullptr);
        add_ln_kernel<<<MD, 128>>>(o1_, q_, o2_, pa2_, dlg + (1 * 3 + 1) * kD, dlb + (1 * 3 + 1) * kD);
        // ffn
        gemm(pa2_, wp_ + o_dw1, db1 + (size_t)1 * kDFF, (float*)pa1_, MD, kDFF, kD, kDFF, 1, nullptr, 1);
        gemm(pa1_, wp_ + o_dw2, db2 + (size_t)1 * kD, q_, MD, kD, kDFF, kD, 0, nullptr);
        add_ln_kernel<<<MD, 128>>>(o2_, q_, do_, pa2_, dlg + (1 * 3 + 2) * kD, dlb + (1 * 3 + 2) * kD);
    }

    // ================= pointer-generator head =================
    attn_out_kernel<<<dim3((kT + 31) / 32, kB * kH), 256>>>(cs_, xe_, t_, kT, kLIN);
    pgen_kernel<<<MD, 128>>>(t_, do_, emb_, ptrw, ptrb, pg_);
    gemm(pa2_, wp_ + o_fw, fb, out, MD, kV, kD, kVE, 0, pg_);
    zero_ext_kernel<<<(MD * kOOV + 255) / 256, 256>>>(out);
    attn_mean_kernel<<<(MD * kLIN + 255) / 256, 256>>>(cs_, am_);
    if (out_size >= MD * kVE + MD * kLIN)
        cudaMemcpyAsync(out + (size_t)MD * kVE, am_,
                        sizeof(float) * MD * kLIN, cudaMemcpyDeviceToDevice, 0);
    scatter_kernel<<<(MD * kLIN + 255) / 256, 256>>>(out, am_, pg_, ext);
}

// round 17
// speedup vs baseline: 1.1219x; 1.1219x over previous
#include <cuda_runtime.h>
#include <cuda_bf16.h>
#include <math.h>
#include <stdint.h>

// ---------------- problem constants ----------------
#define kB    16
#define kLIN  400
#define kT    100
#define kD    512
#define kH    8
#define kDep  64
#define kDFF  2048
#define kV    32000
#define kOOV  100
#define kVE   (kV + kOOV)   // 32100

#define ME (kB * kLIN)      // 6400
#define MD (kB * kT)        // 1600

// packed-weight sizes (uint2 units = 2 elements each)
#define SZ_DD   (kD * kD / 2)
#define SZ_DFF  (kD * kDFF / 2)
#define SZ_FW   (kD * kV / 2)
#define WP_TOTAL (16 * SZ_DD + 6 * SZ_DFF + SZ_FW)

// ---------------- scratch (device globals; no runtime alloc) ----------------
__device__ float g_pe [kLIN * kD];
__device__ float g_xe [ME * kD];
__device__ float g_qkv[ME * 3 * kD / 2 * 2]; // fused QKV / crossQ+crossKV float scratch (ME*1536)
__device__ float g_q  [ME * kD];             // generic float GEMM output
__device__ float g_t  [ME * kD];             // ctx float buffer (pointer head)
__device__ float g_cs [kB * kH * kT * kLIN]; // cross probs (block2)
__device__ float g_xd [MD * kD];
__device__ float g_emb[MD * kD];
__device__ float g_o1 [MD * kD];
__device__ float g_o2 [MD * kD];
__device__ float g_do [MD * kD];
__device__ float g_pg [MD];
__device__ float g_am [MD * kLIN];
__device__ uint2 g_wp [WP_TOTAL];
__device__ uint2 g_pa0[ME * kD / 2];       // packed residual stream (x)
__device__ uint2 g_paT[ME * kD / 2];       // packed attention output
__device__ uint2 g_pa1[ME * kDFF / 2];     // packed ffn hidden
__device__ uint2 g_pa2[MD * kD / 2];       // packed decoder stream

// ---------------- helpers ----------------
__device__ __forceinline__ float warp_sum(float v) {
    #pragma unroll
    for (int o = 16; o > 0; o >>= 1) v += __shfl_xor_sync(0xffffffffu, v, o);
    return v;
}
__device__ __forceinline__ float warp_max(float v) {
    #pragma unroll
    for (int o = 16; o > 0; o >>= 1) v = fmaxf(v, __shfl_xor_sync(0xffffffffu, v, o));
    return v;
}
__device__ __forceinline__ uint2 bfsplit2(float f0, float f1) {
    uint32_t hi;
    asm("cvt.rn.bf16x2.f32 %0, %1, %2;" : "=r"(hi) : "f"(f1), "f"(f0));
    __nv_bfloat162 h = *reinterpret_cast<__nv_bfloat162*>(&hi);
    float r0 = f0 - __bfloat162float(h.x);
    float r1 = f1 - __bfloat162float(h.y);
    uint32_t lo;
    asm("cvt.rn.bf16x2.f32 %0, %1, %2;" : "=r"(lo) : "f"(r1), "f"(r0));
    return make_uint2(hi, lo);
}
__device__ __forceinline__ void mma_bf16(float (&d)[4], const uint32_t (&a)[4], const uint32_t (&b)[2]) {
    asm volatile(
        "mma.sync.aligned.m16n8k16.row.col.f32.bf16.bf16.f32 "
        "{%0,%1,%2,%3},{%4,%5,%6,%7},{%8,%9},{%0,%1,%2,%3};"
        : "+f"(d[0]), "+f"(d[1]), "+f"(d[2]), "+f"(d[3])
        : "r"(a[0]), "r"(a[1]), "r"(a[2]), "r"(a[3]), "r"(b[0]), "r"(b[1]));
}

// ---------------- one-shot weight pack with merged-N layout ----------------
// g_wp layout (uint2 units):
//  enc L0: QKV [256][1536] (3*SZ_DD) | O [256][512] (SZ_DD)
//  enc L1: QKV | O
//  ew1 x2 [256][2048] | ew2 x2 [1024][512]
//  dec L1 self: QKV (3*SZ_DD) | O (SZ_DD)
//  dec L1 cross: Q (SZ_DD) | KV [256][1024] (2*SZ_DD) | O (SZ_DD)
//  dw1 [256][2048] | dw2 [1024][512] | fw [256][32000]
__global__ void pack_all_kernel(const float* __restrict__ eaw, const float* __restrict__ ew1,
                                const float* __restrict__ ew2, const float* __restrict__ daw,
                                const float* __restrict__ dw1, const float* __restrict__ dw2,
                                const float* __restrict__ fw,  uint2* __restrict__ out) {
    long i = (long)blockIdx.x * 256 + threadIdx.x;
    if (i >= (long)WP_TOTAL) return;
    const long DD2L = (long)kD * kD;
    const float* src; long kp, col; int N;
    long j = i;
    if (j < 8L * SZ_DD) {                                   // encoder attn (2 layers)
        long L = j / (4L * SZ_DD); long r = j - L * (4L * SZ_DD);
        const float* base = eaw + L * 4 * DD2L;
        if (r < 3L * SZ_DD) { kp = r / 1536; long nn = r - kp * 1536; src = base + (nn >> 9) * DD2L; col = nn & 511; N = 512; }
        else { long r2 = r - 3L * SZ_DD; kp = r2 >> 9; col = r2 & 511; src = base + 3 * DD2L; N = 512; }
    } else if ((j -= 8L * SZ_DD) < 2L * SZ_DFF) {           // ew1
        long m = j / SZ_DFF, r = j - m * SZ_DFF;
        src = ew1 + m * (long)kD * kDFF; kp = r >> 11; col = r & 2047; N = 2048;
    } else if ((j -= 2L * SZ_DFF) < 2L * SZ_DFF) {          // ew2
        long m = j / SZ_DFF, r = j - m * SZ_DFF;
        src = ew2 + m * (long)kDFF * kD; kp = r >> 9; col = r & 511; N = 512;
    } else if ((j -= 2L * SZ_DFF) < 3L * SZ_DD) {           // dec self QKV (daw mats 8..10)
        kp = j / 1536; long nn = j - kp * 1536; src = daw + (8 + (nn >> 9)) * DD2L; col = nn & 511; N = 512;
    } else if ((j -= 3L * SZ_DD) < (long)SZ_DD) {           // dec self O (mat 11)
        kp = j >> 9; col = j & 511; src = daw + 11 * DD2L; N = 512;
    } else if ((j -= SZ_DD) < (long)SZ_DD) {                // cross Q (mat 12)
        kp = j >> 9; col = j & 511; src = daw + 12 * DD2L; N = 512;
    } else if ((j -= SZ_DD) < 2L * SZ_DD) {                 // cross KV (mats 13,14)
        kp = j >> 10; long nn = j & 1023; src = daw + (13 + (nn >> 9)) * DD2L; col = nn & 511; N = 512;
    } else if ((j -= 2L * SZ_DD) < (long)SZ_DD) {           // cross O (mat 15)
        kp = j >> 9; col = j & 511; src = daw + 15 * DD2L; N = 512;
    } else if ((j -= SZ_DD) < (long)SZ_DFF) {               // dw1 (layer 1)
        src = dw1 + (long)kD * kDFF; kp = j >> 11; col = j & 2047; N = 2048;
    } else if ((j -= SZ_DFF) < (long)SZ_DFF) {              // dw2 (layer 1)
        src = dw2 + (long)kDFF * kD; kp = j >> 9; col = j & 511; N = 512;
    } else {                                                // fw
        j -= SZ_DFF; src = fw; kp = j / kV; col = j - kp * (long)kV; N = kV;
    }
    out[i] = bfsplit2(src[(2 * kp) * (long)N + col], src[(2 * kp + 1) * (long)N + col]);
}

// ---------------- positional encoding ----------------
__global__ void pe_kernel(float* __restrict__ pe) {
    int i = blockIdx.x * 256 + threadIdx.x;
    if (i >= kLIN * kD) return;
    int pos = i / kD, d = i % kD;
    double rate = exp(-(double)(2 * (d / 2)) / (double)kD * log(10000.0));
    double ang  = (double)pos * rate;
    pe[i] = (float)((d & 1) ? cos(ang) : sin(ang));
}

// ---------------- embeddings (emit float + packed) ----------------
__global__ void embed_enc_kernel(const int* __restrict__ idx, const float* __restrict__ emb,
                                 const float* __restrict__ pe, float* __restrict__ x,
                                 uint2* __restrict__ xpk) {
    int i = blockIdx.x * 256 + threadIdx.x;
    if (i >= ME * kD / 2) return;
    int dp = i & 255;
    int bs = i >> 8;
    int s  = bs % kLIN;
    int d  = dp << 1;
    float2 e = *(const float2*)&emb[(size_t)idx[bs] * kD + d];
    float2 p = *(const float2*)&pe[s * kD + d];
    float scale = sqrtf((float)kD);
    float x0 = e.x * scale + p.x, x1 = e.y * scale + p.y;
    *(float2*)&x[(size_t)bs * kD + d] = make_float2(x0, x1);
    xpk[i] = bfsplit2(x0, x1);
}
__global__ void embed_dec_kernel(const int* __restrict__ idx, const float* __restrict__ emb,
                                 const float* __restrict__ pe, float* __restrict__ x,
                                 uint2* __restrict__ xpk, float* __restrict__ eraw) {
    int i = blockIdx.x * 256 + threadIdx.x;
    if (i >= MD * kD / 2) return;
    int dp = i & 255;
    int bs = i >> 8;
    int s  = bs % kT;
    int d  = dp << 1;
    float2 e = *(const float2*)&emb[(size_t)idx[bs] * kD + d];
    float2 p = *(const float2*)&pe[s * kD + d];
    *(float2*)&eraw[(size_t)bs * kD + d] = e;
    float scale = sqrtf((float)kD);
    float x0 = e.x * scale + p.x, x1 = e.y * scale + p.y;
    *(float2*)&x[(size_t)bs * kD + d] = make_float2(x0, x1);
    xpk[i] = bfsplit2(x0, x1);
}

// ---------------- bf16 3-term tensor-core GEMM (proven R10 structure) ----------------
// C[M,N] = A[M,K] @ W[K,N] + bias (+relu, +row-scale | packout). Pre-packed hi/lo.
// Tile 64x128, BK=32 (16 kpairs), 256 threads = 8 warps (2M x 4N), warp 32x32.
__global__ void __launch_bounds__(256)
gemm_bf16_kernel(const uint2* __restrict__ Ap, const uint2* __restrict__ Wp,
                 const float* __restrict__ bias, float* __restrict__ C,
                 int M, int N, int K, int ldc, int relu, const float* __restrict__ rs,
                 int packout) {
    __shared__ uint2 As[16][68];
    __shared__ uint2 Bs[16][132];

    const int t = threadIdx.x, lane = t & 31, wid = t >> 5;
    const int wm = wid & 1, wn = wid >> 1;
    const int g = lane >> 2, c = lane & 3;
    const int bm = blockIdx.y << 6, bn = blockIdx.x << 7;
    const int a_row = t & 63, a_kq = (t >> 6) << 2;
    const int b_kp = t >> 4, b_n = (t & 15) << 1;
    const int Kp = K >> 1;

    const uint2* aptr = Ap + (size_t)(bm + a_row) * Kp + a_kq;
    float acc[2][4][4] = {};

    for (int kp0 = 0; kp0 < Kp; kp0 += 16) {
        uint4 av0 = *(const uint4*)(aptr + kp0);
        uint4 av1 = *(const uint4*)(aptr + kp0 + 2);
        const uint2* wrow = Wp + (size_t)(kp0 + b_kp) * N + bn + b_n;
        uint4 bv0 = *(const uint4*)(wrow);
        uint4 bv1 = *(const uint4*)(wrow + 32);
        uint4 bv2 = *(const uint4*)(wrow + 64);
        uint4 bv3 = *(const uint4*)(wrow + 96);
        __syncthreads();
        As[a_kq + 0][a_row] = make_uint2(av0.x, av0.y);
        As[a_kq + 1][a_row] = make_uint2(av0.z, av0.w);
        As[a_kq + 2][a_row] = make_uint2(av1.x, av1.y);
        As[a_kq + 3][a_row] = make_uint2(av1.z, av1.w);
        *(uint4*)&Bs[b_kp][b_n]      = bv0;
        *(uint4*)&Bs[b_kp][b_n + 32] = bv1;
        *(uint4*)&Bs[b_kp][b_n + 64] = bv2;
        *(uint4*)&Bs[b_kp][b_n + 96] = bv3;
        __syncthreads();
        #pragma unroll
        for (int s = 0; s < 2; ++s) {
            const int sb = s << 3;
            uint2 af[2][4], bf[4][2];
            #pragma unroll
            for (int mi = 0; mi < 2; ++mi) {
                int m = (wm << 5) + (mi << 4) + g;
                af[mi][0] = As[sb + c][m];
                af[mi][1] = As[sb + c][m + 8];
                af[mi][2] = As[sb + c + 4][m];
                af[mi][3] = As[sb + c + 4][m + 8];
            }
            #pragma unroll
            for (int ni = 0; ni < 4; ++ni) {
                int n = (wn << 5) + (ni << 3) + g;
                bf[ni][0] = Bs[sb + c][n];
                bf[ni][1] = Bs[sb + c + 4][n];
            }
            #pragma unroll
            for (int mi = 0; mi < 2; ++mi) {
                uint32_t ah[4] = {af[mi][0].x, af[mi][1].x, af[mi][2].x, af[mi][3].x};
                uint32_t al[4] = {af[mi][0].y, af[mi][1].y, af[mi][2].y, af[mi][3].y};
                #pragma unroll
                for (int ni = 0; ni < 4; ++ni) {
                    uint32_t bh[2] = {bf[ni][0].x, bf[ni][1].x};
                    uint32_t bl[2] = {bf[ni][0].y, bf[ni][1].y};
                    mma_bf16(acc[mi][ni], al, bh);
                    mma_bf16(acc[mi][ni], ah, bl);
                    mma_bf16(acc[mi][ni], ah, bh);
                }
            }
        }
    }

    // ---- epilogue ----
    #pragma unroll
    for (int mi = 0; mi < 2; ++mi) {
        int r0 = bm + (wm << 5) + (mi << 4) + g;
        float s0 = rs ? rs[r0] : 1.0f;
        float s1 = rs ? rs[r0 + 8] : 1.0f;
        #pragma unroll
        for (int ni = 0; ni < 4; ++ni) {
            int c0 = bn + (wn << 5) + (ni << 3) + (c << 1);
            float bb0 = bias[c0], bb1 = bias[c0 + 1];
            float v0 = acc[mi][ni][0] + bb0, v1 = acc[mi][ni][1] + bb1;
            float v2 = acc[mi][ni][2] + bb0, v3 = acc[mi][ni][3] + bb1;
            if (relu) {
                v0 = fmaxf(v0, 0.0f); v1 = fmaxf(v1, 0.0f);
                v2 = fmaxf(v2, 0.0f); v3 = fmaxf(v3, 0.0f);
            }
            if (packout) {
                uint2* Cp = (uint2*)C;
                int ldp = ldc >> 1;
                Cp[(size_t)r0 * ldp + (c0 >> 1)]       = bfsplit2(v0 * s0, v1 * s0);
                Cp[(size_t)(r0 + 8) * ldp + (c0 >> 1)] = bfsplit2(v2 * s1, v3 * s1);
            } else {
                *(float2*)&C[(size_t)r0 * ldc + c0]       = make_float2(v0 * s0, v1 * s0);
                *(float2*)&C[(size_t)(r0 + 8) * ldc + c0] = make_float2(v2 * s1, v3 * s1);
            }
        }
    }
}

// ---------------- fused attention: scores -> softmax -> P@V, packed output ------
// ldq / ldkv: row strides (in floats) of the Q and K/V buffers (fused QKV support).
#define ATTN_SMEM_BYTES ((32*408 + 32*68 + 32*68) * 4)
__global__ void __launch_bounds__(256)
fused_attn_kernel(const float* __restrict__ Q, const float* __restrict__ Kt,
                  const float* __restrict__ V, uint2* __restrict__ Opk,
                  int Sq, int Sk, const float* __restrict__ mask, int mode,
                  float* __restrict__ Pout, int ldq, int ldkv) {
    extern __shared__ float sm_f[];
    float (*Ss)[408] = (float(*)[408])sm_f;
    float (*Qs)[68]  = (float(*)[68])(sm_f + 32 * 408);
    float (*Ks)[68]  = (float(*)[68])(sm_f + 32 * 408 + 32 * 68);

    const int tid = threadIdx.x;
    const int bh = blockIdx.y, b = bh >> 3, h = bh & 7;
    const int q0 = blockIdx.x * 32;

    for (int i = tid; i < 32 * 16; i += 256) {
        int r = i >> 4, c4 = (i & 15) << 2;
        float4 qv = make_float4(0, 0, 0, 0);
        if (q0 + r < Sq) qv = *(const float4*)&Q[((size_t)(b * Sq + q0 + r)) * ldq + h * kDep + c4];
        *(float4*)&Qs[r][c4] = qv;
    }

    const int tx = tid & 15, ty = tid >> 4;
    for (int k0 = 0; k0 < Sk; k0 += 32) {
        for (int i = tid; i < 32 * 16; i += 256) {
            int r = i >> 4, c4 = (i & 15) << 2;
            float4 kv = make_float4(0, 0, 0, 0);
            if (k0 + r < Sk) kv = *(const float4*)&Kt[((size_t)(b * Sk + k0 + r)) * ldkv + h * kDep + c4];
            *(float4*)&Ks[r][c4] = kv;
        }
        __syncthreads();
        float acc[2][2] = {};
        #pragma unroll
        for (int d4 = 0; d4 < kDep; d4 += 4) {
            float4 a0 = *(const float4*)&Qs[ty * 2 + 0][d4];
            float4 a1 = *(const float4*)&Qs[ty * 2 + 1][d4];
            float4 b0 = *(const float4*)&Ks[tx * 2 + 0][d4];
            float4 b1 = *(const float4*)&Ks[tx * 2 + 1][d4];
            acc[0][0] += a0.x*b0.x + a0.y*b0.y + a0.z*b0.z + a0.w*b0.w;
            acc[0][1] += a0.x*b1.x + a0.y*b1.y + a0.z*b1.z + a0.w*b1.w;
            acc[1][0] += a1.x*b0.x + a1.y*b0.y + a1.z*b0.z + a1.w*b0.w;
            acc[1][1] += a1.x*b1.x + a1.y*b1.y + a1.z*b1.z + a1.w*b1.w;
        }
        #pragma unroll
        for (int i = 0; i < 2; ++i) {
            int qg = q0 + ty * 2 + i;
            #pragma unroll
            for (int j = 0; j < 2; ++j) {
                int kg = k0 + tx * 2 + j;
                if (qg < Sq && kg < Sk) {
                    float vv = acc[i][j] * 0.125f;
                    float mk = (mode == 0) ? mask[(size_t)b * Sk + kg]
                                           : mask[((size_t)b * Sq + qg) * Sk + kg];
                    Ss[ty * 2 + i][kg] = vv + mk * (-1e9f);
                }
            }
        }
        __syncthreads();
    }

    {
        const int wid = tid >> 5, lane = tid & 31;
        #pragma unroll
        for (int rr = 0; rr < 4; ++rr) {
            int r = (wid << 2) + rr;
            if (q0 + r < Sq) {
                float m = -1e30f;
                for (int i = lane; i < Sk; i += 32) m = fmaxf(m, Ss[r][i]);
                m = warp_max(m);
                float s = 0.0f;
                for (int i = lane; i < Sk; i += 32) { float e = __expf(Ss[r][i] - m); Ss[r][i] = e; s += e; }
                s = warp_sum(s);
                float inv = 1.0f / s;
                for (int i = lane; i < Sk; i += 32) Ss[r][i] *= inv;
            }
        }
    }
    __syncthreads();

    if (Pout) {
        for (int idx = tid; idx < 32 * Sk; idx += 256) {
            int r = idx / Sk, col = idx - r * Sk;
            if (q0 + r < Sq)
                Pout[((size_t)bh * Sq + q0 + r) * Sk + col] = Ss[r][col];
        }
    }

    const int dcol = tid & 63, qb = tid >> 6;
    float acc[8] = {};
    for (int k0 = 0; k0 < Sk; k0 += 32) {
        for (int i = tid; i < 32 * 16; i += 256) {
            int r = i >> 4, c4 = (i & 15) << 2;
            float4 v4 = make_float4(0, 0, 0, 0);
            if (k0 + r < Sk) v4 = *(const float4*)&V[((size_t)(b * Sk + k0 + r)) * ldkv + h * kDep + c4];
            *(float4*)&Ks[r][c4] = v4;
        }
        __syncthreads();
        int klim = Sk - k0; if (klim > 32) klim = 32;
        for (int kk = 0; kk < klim; ++kk) {
            float vv = Ks[kk][dcol];
            #pragma unroll
            for (int j = 0; j < 8; ++j)
                acc[j] = fmaf(Ss[qb + (j << 2)][k0 + kk], vv, acc[j]);
        }
        __syncthreads();
    }
    #pragma unroll
    for (int j = 0; j < 8; ++j) {
        float other = __shfl_xor_sync(0xffffffffu, acc[j], 1);
        int qg = q0 + qb + (j << 2);
        if (((dcol & 1) == 0) && qg < Sq) {
            Opk[((size_t)(b * Sq + qg)) * (kD / 2) + ((h * kDep + dcol) >> 1)] =
                bfsplit2(acc[j], other);
        }
    }
}

// ---------------- context einsum: O = P @ V (float, pointer head only) ----------
__global__ void __launch_bounds__(256)
attn_out_kernel(const float* __restrict__ P, const float* __restrict__ V,
                float* __restrict__ O, int Sq, int Sk) {
    __shared__ float Ps[32][33];
    __shared__ float Vs[32][64];
    int tid = threadIdx.x;
    int bh = blockIdx.y, b = bh >> 3, h = bh & 7;
    int q0 = blockIdx.x * 32;
    const float* p = P + (size_t)bh * Sq * Sk;
    int dcol = tid & 63, qb = tid >> 6;
    float acc[8] = {};
    for (int k0 = 0; k0 < Sk; k0 += 32) {
        {
            int r = tid >> 3, cc = (tid & 7) << 2;
            int qg = q0 + r, kg = k0 + cc;
            float4 v4 = make_float4(0, 0, 0, 0);
            if (qg < Sq && kg < Sk)
                v4 = *(const float4*)&p[(size_t)qg * Sk + kg];
            Ps[r][cc] = v4.x; Ps[r][cc + 1] = v4.y; Ps[r][cc + 2] = v4.z; Ps[r][cc + 3] = v4.w;
        }
        for (int i = tid; i < 32 * 16; i += 256) {
            int r = i >> 4, c4 = (i & 15) << 2;
            int kg = k0 + r;
            float4 v4 = make_float4(0, 0, 0, 0);
            if (kg < Sk) v4 = *(const float4*)&V[((size_t)(b * Sk + kg)) * kD + h * kDep + c4];
            *(float4*)&Vs[r][c4] = v4;
        }
        __syncthreads();
        #pragma unroll
        for (int kk = 0; kk < 32; ++kk) {
            float vv = Vs[kk][dcol];
            #pragma unroll
            for (int j = 0; j < 8; ++j)
                acc[j] = fmaf(Ps[qb + (j << 2)][kk], vv, acc[j]);
        }
        __syncthreads();
    }
    #pragma unroll
    for (int j = 0; j < 8; ++j) {
        int qg = q0 + qb + (j << 2);
        if (qg < Sq) O[((size_t)(b * Sq + qg)) * kD + h * kDep + dcol] = acc[j];
    }
}

// ---------------- y = LN(x + a) * g + b, emits float + packed ----------------
__global__ void add_ln_kernel(const float* __restrict__ x, const float* __restrict__ a,
                              float* __restrict__ y, uint2* __restrict__ ypk,
                              const float* __restrict__ g, const float* __restrict__ bb) {
    int row = blockIdx.x, tid = threadIdx.x;
    size_t base = (size_t)row * kD;
    int d0 = tid << 2;
    float4 xv = *(const float4*)&x[base + d0];
    float4 av = *(const float4*)&a[base + d0];
    float v0 = xv.x + av.x, v1 = xv.y + av.y, v2 = xv.z + av.z, v3 = xv.w + av.w;
    float s = v0 + v1 + v2 + v3;
    float s2 = v0*v0 + v1*v1 + v2*v2 + v3*v3;
    __shared__ float shs[4], shs2[4];
    s = warp_sum(s); s2 = warp_sum(s2);
    if ((tid & 31) == 0) { shs[tid >> 5] = s; shs2[tid >> 5] = s2; }
    __syncthreads();
    float S = shs[0] + shs[1] + shs[2] + shs[3];
    float S2 = shs2[0] + shs2[1] + shs2[2] + shs2[3];
    float mu = S * (1.0f / kD);
    float var = S2 * (1.0f / kD) - mu * mu;
    float rstd = rsqrtf(var + 1e-6f);
    float4 gv = *(const float4*)&g[d0];
    float4 bv = *(const float4*)&bb[d0];
    float y0 = (v0 - mu) * rstd * gv.x + bv.x;
    float y1 = (v1 - mu) * rstd * gv.y + bv.y;
    float y2 = (v2 - mu) * rstd * gv.z + bv.z;
    float y3 = (v3 - mu) * rstd * gv.w + bv.w;
    *(float4*)&y[base + d0] = make_float4(y0, y1, y2, y3);
    uint2 p0 = bfsplit2(y0, y1), p1 = bfsplit2(y2, y3);
    *(uint4*)&ypk[(size_t)row * (kD / 2) + (tid << 1)] = make_uint4(p0.x, p0.y, p1.x, p1.y);
}

// ---------------- p_gen ----------------
__global__ void pgen_kernel(const float* __restrict__ ctx, const float* __restrict__ dec,
                            const float* __restrict__ emb, const float* __restrict__ w,
                            const float* __restrict__ bvec, float* __restrict__ pg) {
    int row = blockIdx.x, tid = threadIdx.x;
    float s = 0.0f;
    for (int d = tid; d < kD; d += 128) {
        size_t o = (size_t)row * kD + d;
        s += ctx[o] * w[d] + dec[o] * w[kD + d] + emb[o] * w[2 * kD + d];
    }
    __shared__ float sh[4];
    s = warp_sum(s);
    if ((tid & 31) == 0) sh[tid >> 5] = s;
    __syncthreads();
    if (tid == 0) {
        float t = sh[0] + sh[1] + sh[2] + sh[3] + bvec[0] + bvec[1] + bvec[2];
        pg[row] = 1.0f / (1.0f + expf(-t));
    }
}

// ---------------- attn_mean ----------------
__global__ void attn_mean_kernel(const float* __restrict__ P, float* __restrict__ am) {
    int i = blockIdx.x * 256 + threadIdx.x;
    if (i >= MD * kLIN) return;
    int l = i % kLIN;
    int bt = i / kLIN;
    int b = bt / kT, t = bt % kT;
    float s = 0.0f;
    #pragma unroll
    for (int h = 0; h < kH; ++h)
        s += P[(((size_t)(b * kH + h) * kT) + t) * kLIN + l];
    am[i] = s * (1.0f / kH);
}

// ---------------- zero extension columns ----------------
__global__ void zero_ext_kernel(float* __restrict__ out) {
    int i = blockIdx.x * 256 + threadIdx.x;
    if (i >= MD * kOOV) return;
    int row = i / kOOV, c = i % kOOV;
    out[(size_t)row * kVE + kV + c] = 0.0f;
}

// ---------------- copy scatter ----------------
__global__ void scatter_kernel(float* __restrict__ out, const float* __restrict__ am,
                               const float* __restrict__ pg, const int* __restrict__ ext) {
    int i = blockIdx.x * 256 + threadIdx.x;
    if (i >= MD * kLIN) return;
    int l = i % kLIN;
    int bt = i / kLIN;
    int b = bt / kT;
    float v = (1.0f - pg[bt]) * am[i];
    int vi = ext[b * kLIN + l];
    atomicAdd(&out[(size_t)bt * kVE + vi], v);
}

// ---------------- host orchestration ----------------
extern "C" void kernel_launch(void* const* d_in, const int* in_sizes, int n_in,
                              void* d_out, int out_size) {
    int off = (n_in > 6 && in_sizes[6] == 1) ? 1 : 0;
    const int*   inp      = (const int*)d_in[0];
    const int*   tar      = (const int*)d_in[1];
    const int*   ext      = (const int*)d_in[2];
    const float* enc_mask = (const float*)d_in[3];
    const float* la_mask  = (const float*)d_in[4];
    const float* dec_mask = (const float*)d_in[5];
    const float* emb_enc  = (const float*)d_in[6 + off];
    const float* emb_dec  = (const float*)d_in[7 + off];
    const float* eaw = (const float*)d_in[8 + off];
    const float* eab = (const float*)d_in[9 + off];
    const float* ew1 = (const float*)d_in[10 + off];
    const float* eb1 = (const float*)d_in[11 + off];
    const float* ew2 = (const float*)d_in[12 + off];
    const float* eb2 = (const float*)d_in[13 + off];
    const float* elg = (const float*)d_in[14 + off];
    const float* elb = (const float*)d_in[15 + off];
    const float* daw = (const float*)d_in[16 + off];
    const float* dab = (const float*)d_in[17 + off];
    const float* dw1 = (const float*)d_in[18 + off];
    const float* db1 = (const float*)d_in[19 + off];
    const float* dw2 = (const float*)d_in[20 + off];
    const float* db2 = (const float*)d_in[21 + off];
    const float* dlg = (const float*)d_in[22 + off];
    const float* dlb = (const float*)d_in[23 + off];
    const float* ptrw = (const float*)d_in[24 + off];
    const float* ptrb = (const float*)d_in[25 + off];
    const float* fw  = (const float*)d_in[26 + off];
    const float* fb  = (const float*)d_in[27 + off];
    float* out = (float*)d_out;

    float *pe_, *xe_, *qkv_, *q_, *t_, *cs_, *xd_, *emb_, *o1_, *o2_, *do_, *pg_, *am_;
    uint2 *wp_, *pa0_, *paT_, *pa1_, *pa2_;
    cudaGetSymbolAddress((void**)&pe_,  g_pe);
    cudaGetSymbolAddress((void**)&xe_,  g_xe);
    cudaGetSymbolAddress((void**)&qkv_, g_qkv);
    cudaGetSymbolAddress((void**)&q_,   g_q);
    cudaGetSymbolAddress((void**)&t_,   g_t);
    cudaGetSymbolAddress((void**)&cs_,  g_cs);
    cudaGetSymbolAddress((void**)&xd_,  g_xd);
    cudaGetSymbolAddress((void**)&emb_, g_emb);
    cudaGetSymbolAddress((void**)&o1_,  g_o1);
    cudaGetSymbolAddress((void**)&o2_,  g_o2);
    cudaGetSymbolAddress((void**)&do_,  g_do);
    cudaGetSymbolAddress((void**)&pg_,  g_pg);
    cudaGetSymbolAddress((void**)&am_,  g_am);
    cudaGetSymbolAddress((void**)&wp_,  g_wp);
    cudaGetSymbolAddress((void**)&pa0_, g_pa0);
    cudaGetSymbolAddress((void**)&paT_, g_paT);
    cudaGetSymbolAddress((void**)&pa1_, g_pa1);
    cudaGetSymbolAddress((void**)&pa2_, g_pa2);

    cudaFuncSetAttribute(fused_attn_kernel, cudaFuncAttributeMaxDynamicSharedMemorySize, ATTN_SMEM_BYTES);

    // packed weight offsets (uint2 units) — must match pack_all_kernel layout
    const size_t o_eqkv0 = 0;
    const size_t o_eo0   = 3 * (size_t)SZ_DD;
    const size_t o_eqkv1 = 4 * (size_t)SZ_DD;
    const size_t o_eo1   = 7 * (size_t)SZ_DD;
    const size_t o_ew1   = 8 * (size_t)SZ_DD;
    const size_t o_ew2   = o_ew1 + 2 * (size_t)SZ_DFF;
    const size_t o_dqkv  = o_ew2 + 2 * (size_t)SZ_DFF;
    const size_t o_dso   = o_dqkv + 3 * (size_t)SZ_DD;
    const size_t o_cq    = o_dso + (size_t)SZ_DD;
    const size_t o_ckv   = o_cq + (size_t)SZ_DD;
    const size_t o_co    = o_ckv + 2 * (size_t)SZ_DD;
    const size_t o_dw1   = o_co + (size_t)SZ_DD;
    const size_t o_dw2   = o_dw1 + (size_t)SZ_DFF;
    const size_t o_fw    = o_dw2 + (size_t)SZ_DFF;

    auto gemm = [&](const uint2* Ap, const uint2* Wp, const float* bias, float* C,
                    int M, int N, int K, int ldc, int relu, const float* rs, int packout = 0) {
        dim3 grid(N / 128, M / 64);
        gemm_bf16_kernel<<<grid, 256>>>(Ap, Wp, bias, C, M, N, K, ldc, relu, rs, packout);
    };
    auto attn = [&](const float* Q, const float* Kt, const float* V, uint2* Opk,
                    int Sq, int Sk, const float* mask, int mode, float* Pout,
                    int ldq, int ldkv) {
        dim3 grid((Sq + 31) / 32, kB * kH);
        fused_attn_kernel<<<grid, 256, ATTN_SMEM_BYTES>>>(Q, Kt, V, Opk, Sq, Sk, mask, mode, Pout, ldq, ldkv);
    };

    // -------- pack ALL weights in one launch (merged-N layout) --------
    pack_all_kernel<<<(WP_TOTAL + 255) / 256, 256>>>(eaw, ew1, ew2, daw, dw1, dw2, fw, wp_);

    pe_kernel<<<(kLIN * kD + 255) / 256, 256>>>(pe_);
    embed_enc_kernel<<<(ME * kD / 2 + 255) / 256, 256>>>(inp, emb_enc, pe_, xe_, pa0_);

    // ================= encoder =================
    for (int i = 0; i < 2; ++i) {
        const size_t o_qkv = i ? o_eqkv1 : o_eqkv0;
        const size_t o_o   = i ? o_eo1   : o_eo0;
        const float* b = eab + (size_t)i * 4 * kD;   // q,k,v biases contiguous (1536), then o
        gemm(pa0_, wp_ + o_qkv, b, qkv_, ME, 3 * kD, kD, 3 * kD, 0, nullptr);
        attn(qkv_, qkv_ + kD, qkv_ + 2 * kD, paT_, kLIN, kLIN, enc_mask, 0, nullptr, 3 * kD, 3 * kD);
        gemm(paT_, wp_ + o_o, b + 3 * kD, q_, ME, kD, kD, kD, 0, nullptr);
        add_ln_kernel<<<ME, 128>>>(xe_, q_, xe_, pa0_, elg + (i * 2 + 0) * kD, elb + (i * 2 + 0) * kD);
        gemm(pa0_, wp_ + o_ew1 + (size_t)i * SZ_DFF, eb1 + (size_t)i * kDFF,
             (float*)pa1_, ME, kDFF, kD, kDFF, 1, nullptr, 1);
        gemm(pa1_, wp_ + o_ew2 + (size_t)i * SZ_DFF, eb2 + (size_t)i * kD, q_, ME, kD, kDFF, kD, 0, nullptr);
        add_ln_kernel<<<ME, 128>>>(xe_, q_, xe_, pa0_, elg + (i * 2 + 1) * kD, elb + (i * 2 + 1) * kD);
    }
    // pa0_ now holds the packed final encoder output (for cross K/V)

    // ================= decoder (only layer 1 live; xd never updated in ref) ========
    embed_dec_kernel<<<(MD * kD / 2 + 255) / 256, 256>>>(tar, emb_dec, pe_, xd_, pa2_, emb_);
    {
        const float* b0 = dab + (size_t)(1 * 2 + 0) * 4 * kD;
        const float* b1 = dab + (size_t)(1 * 2 + 1) * 4 * kD;
        // self attention (fused QKV)
        gemm(pa2_, wp_ + o_dqkv, b0, qkv_, MD, 3 * kD, kD, 3 * kD, 0, nullptr);
        attn(qkv_, qkv_ + kD, qkv_ + 2 * kD, pa2_, kT, kT, la_mask, 1, nullptr, 3 * kD, 3 * kD);
        gemm(pa2_, wp_ + o_dso, b0 + 3 * kD, q_, MD, kD, kD, kD, 0, nullptr);
        add_ln_kernel<<<MD, 128>>>(xd_, q_, o1_, pa2_, dlg + (1 * 3 + 0) * kD, dlb + (1 * 3 + 0) * kD);
        // cross attention: Q from decoder stream; fused KV from encoder
        float* cq = qkv_;                      // MD x 512
        float* kv = qkv_ + (size_t)MD * kD;    // ME x 1024
        gemm(pa2_, wp_ + o_cq, b1, cq, MD, kD, kD, kD, 0, nullptr);
        gemm(pa0_, wp_ + o_ckv, b1 + kD, kv, ME, 2 * kD, kD, 2 * kD, 0, nullptr);
        attn(cq, kv, kv + kD, pa2_, kT, kLIN, dec_mask, 0, cs_, kD, 2 * kD);
        gemm(pa2_, wp_ + o_co, b1 + 3 * kD, q_, MD, kD, kD, kD, 0, nullptr);
        add_ln_kernel<<<MD, 128>>>(o1_, q_, o2_, pa2_, dlg + (1 * 3 + 1) * kD, dlb + (1 * 3 + 1) * kD);
        // ffn
        gemm(pa2_, wp_ + o_dw1, db1 + (size_t)1 * kDFF, (float*)pa1_, MD, kDFF, kD, kDFF, 1, nullptr, 1);
        gemm(pa1_, wp_ + o_dw2, db2 + (size_t)1 * kD, q_, MD, kD, kDFF, kD, 0, nullptr);
        add_ln_kernel<<<MD, 128>>>(o2_, q_, do_, pa2_, dlg + (1 * 3 + 2) * kD, dlb + (1 * 3 + 2) * kD);
    }

    // ================= pointer-generator head =================
    attn_out_kernel<<<dim3((kT + 31) / 32, kB * kH), 256>>>(cs_, xe_, t_, kT, kLIN);
    pgen_kernel<<<MD, 128>>>(t_, do_, emb_, ptrw, ptrb, pg_);
    gemm(pa2_, wp_ + o_fw, fb, out, MD, kV, kD, kVE, 0, pg_);
    zero_ext_kernel<<<(MD * kOOV + 255) / 256, 256>>>(out);
    attn_mean_kernel<<<(MD * kLIN + 255) / 256, 256>>>(cs_, am_);
    if (out_size >= MD * kVE + MD * kLIN)
        cudaMemcpyAsync(out + (size_t)MD * kVE, am_,
                        sizeof(float) * MD * kLIN, cudaMemcpyDeviceToDevice, 0);
    scatter_kernel<<<(MD * kLIN + 255) / 256, 256>>>(out, am_, pg_, ext);
}